// round 1
// baseline (speedup 1.0000x reference)
#include <cuda_runtime.h>
#include <cuda_bf16.h>
#include <math_constants.h>

// Problem constants
#define Bn 32
#define Sn 512
#define En 256
#define Hn 8
#define HEn (Hn * En)        // 2048
#define Mn (Bn * Sn)         // 16384
#define BHn (Bn * Hn)        // 256

// GEMM tile config
#define BM 64
#define BN 64
#define BK 16
#define NTHREADS 256

// ---------------------------------------------------------------------------
// Scratch (device globals; allocation-free per harness rules)
// ---------------------------------------------------------------------------
__device__ float g_Q[(size_t)BHn * Sn * En];   // [B,H,S,E] 128 MB
__device__ float g_K[(size_t)BHn * Sn * En];   // 128 MB (padding-masked)
__device__ float g_V[(size_t)BHn * Sn * En];   // 128 MB
__device__ float g_Sc[(size_t)BHn * Sn * Sn];  // [B,H,S,S] 256 MB
__device__ float g_C[(size_t)Mn * HEn];        // concat [B,S,H*E] 128 MB

// ---------------------------------------------------------------------------
// Kernel 1: per-head projection  Out[b,h,s,d] = sum_e X[b,s,e] * W[h,d,e]
// NT GEMM: A = X [M=16384, K=256], B = W_h [N=256(d), K=256(e)]
// Optional padding mask (for K projection) applied per output row at store.
// ---------------------------------------------------------------------------
__global__ __launch_bounds__(NTHREADS)
void proj_kernel(const float* __restrict__ X, const float* __restrict__ W,
                 const float* __restrict__ pad, float* __restrict__ Out)
{
    __shared__ float As[BK][BM];
    __shared__ float Bs[BK][BN];

    const int h  = blockIdx.z;
    const int m0 = blockIdx.y * BM;
    const int n0 = blockIdx.x * BN;
    const float* Wh = W + (size_t)h * En * En;

    const int tid  = threadIdx.x;
    const int trow = tid >> 4;          // 0..15
    const int tcol = tid & 15;          // 0..15
    const int lrow = tid >> 2;          // 0..63 (load row)
    const int lcq  = tid & 3;           // 0..3  (which float4 along K)

    float acc[4][4] = {};

    for (int k0 = 0; k0 < En; k0 += BK) {
        float4 av = *reinterpret_cast<const float4*>(
            X + (size_t)(m0 + lrow) * En + k0 + lcq * 4);
        As[lcq * 4 + 0][lrow] = av.x;
        As[lcq * 4 + 1][lrow] = av.y;
        As[lcq * 4 + 2][lrow] = av.z;
        As[lcq * 4 + 3][lrow] = av.w;

        float4 bv = *reinterpret_cast<const float4*>(
            Wh + (size_t)(n0 + lrow) * En + k0 + lcq * 4);
        Bs[lcq * 4 + 0][lrow] = bv.x;
        Bs[lcq * 4 + 1][lrow] = bv.y;
        Bs[lcq * 4 + 2][lrow] = bv.z;
        Bs[lcq * 4 + 3][lrow] = bv.w;

        __syncthreads();
        #pragma unroll
        for (int kk = 0; kk < BK; kk++) {
            float4 a4 = *reinterpret_cast<float4*>(&As[kk][trow * 4]);
            float4 b4 = *reinterpret_cast<float4*>(&Bs[kk][tcol * 4]);
            float a[4] = {a4.x, a4.y, a4.z, a4.w};
            float b[4] = {b4.x, b4.y, b4.z, b4.w};
            #pragma unroll
            for (int i = 0; i < 4; i++)
                #pragma unroll
                for (int j = 0; j < 4; j++)
                    acc[i][j] = fmaf(a[i], b[j], acc[i][j]);
        }
        __syncthreads();
    }

    #pragma unroll
    for (int i = 0; i < 4; i++) {
        const int gm = m0 + trow * 4 + i;     // flattened b*S+s
        const int b  = gm / Sn;
        const int s  = gm % Sn;
        const float scale = pad ? pad[gm] : 1.0f;
        float4 o;
        o.x = acc[i][0] * scale;
        o.y = acc[i][1] * scale;
        o.z = acc[i][2] * scale;
        o.w = acc[i][3] * scale;
        *reinterpret_cast<float4*>(
            Out + (((size_t)(b * Hn + h) * Sn + s) * En) + n0 + tcol * 4) = o;
    }
}

// ---------------------------------------------------------------------------
// Kernel 2: scores[bh][q][k] = (Q[bh][q]·K[bh][k]) / sqrt(E) + causal
// NT GEMM per (b,h): M=N=512, K=256
// ---------------------------------------------------------------------------
__global__ __launch_bounds__(NTHREADS)
void scores_kernel(const float* __restrict__ Q, const float* __restrict__ Kp,
                   float* __restrict__ Sc)
{
    __shared__ float As[BK][BM];
    __shared__ float Bs[BK][BN];

    const int bh = blockIdx.z;
    const int m0 = blockIdx.y * BM;
    const int n0 = blockIdx.x * BN;
    const float* A = Q  + (size_t)bh * Sn * En;
    const float* Bm = Kp + (size_t)bh * Sn * En;

    const int tid  = threadIdx.x;
    const int trow = tid >> 4;
    const int tcol = tid & 15;
    const int lrow = tid >> 2;
    const int lcq  = tid & 3;

    float acc[4][4] = {};

    for (int k0 = 0; k0 < En; k0 += BK) {
        float4 av = *reinterpret_cast<const float4*>(
            A + (size_t)(m0 + lrow) * En + k0 + lcq * 4);
        As[lcq * 4 + 0][lrow] = av.x;
        As[lcq * 4 + 1][lrow] = av.y;
        As[lcq * 4 + 2][lrow] = av.z;
        As[lcq * 4 + 3][lrow] = av.w;

        float4 bv = *reinterpret_cast<const float4*>(
            Bm + (size_t)(n0 + lrow) * En + k0 + lcq * 4);
        Bs[lcq * 4 + 0][lrow] = bv.x;
        Bs[lcq * 4 + 1][lrow] = bv.y;
        Bs[lcq * 4 + 2][lrow] = bv.z;
        Bs[lcq * 4 + 3][lrow] = bv.w;

        __syncthreads();
        #pragma unroll
        for (int kk = 0; kk < BK; kk++) {
            float4 a4 = *reinterpret_cast<float4*>(&As[kk][trow * 4]);
            float4 b4 = *reinterpret_cast<float4*>(&Bs[kk][tcol * 4]);
            float a[4] = {a4.x, a4.y, a4.z, a4.w};
            float b[4] = {b4.x, b4.y, b4.z, b4.w};
            #pragma unroll
            for (int i = 0; i < 4; i++)
                #pragma unroll
                for (int j = 0; j < 4; j++)
                    acc[i][j] = fmaf(a[i], b[j], acc[i][j]);
        }
        __syncthreads();
    }

    const float inv_sqrt_e = 0.0625f;  // 1/sqrt(256)
    #pragma unroll
    for (int i = 0; i < 4; i++) {
        const int mq = m0 + trow * 4 + i;   // query index
        float4 o;
        float* oo = &o.x;
        #pragma unroll
        for (int j = 0; j < 4; j++) {
            const int kk = n0 + tcol * 4 + j;  // key index
            float s = acc[i][j] * inv_sqrt_e;
            if (kk > mq) s += -1e9f;
            oo[j] = s;
        }
        *reinterpret_cast<float4*>(
            Sc + (size_t)bh * Sn * Sn + (size_t)mq * Sn + n0 + tcol * 4) = o;
    }
}

// ---------------------------------------------------------------------------
// Kernel 3: row softmax over last dim (512), one block per row
// ---------------------------------------------------------------------------
__global__ __launch_bounds__(256)
void softmax_kernel(float* __restrict__ Sc)
{
    __shared__ float red[8];
    const size_t row = blockIdx.x;
    float* p = Sc + row * Sn;
    const int tid = threadIdx.x;

    float v0 = p[tid];
    float v1 = p[tid + 256];

    // max reduce
    float m = fmaxf(v0, v1);
    #pragma unroll
    for (int o = 16; o; o >>= 1) m = fmaxf(m, __shfl_xor_sync(0xffffffffu, m, o));
    if ((tid & 31) == 0) red[tid >> 5] = m;
    __syncthreads();
    if (tid < 32) {
        float x = (tid < 8) ? red[tid] : -CUDART_INF_F;
        #pragma unroll
        for (int o = 4; o; o >>= 1) x = fmaxf(x, __shfl_xor_sync(0xffffffffu, x, o));
        if (tid == 0) red[0] = x;
    }
    __syncthreads();
    m = red[0];
    __syncthreads();

    float e0 = __expf(v0 - m);
    float e1 = __expf(v1 - m);

    // sum reduce
    float s = e0 + e1;
    #pragma unroll
    for (int o = 16; o; o >>= 1) s += __shfl_xor_sync(0xffffffffu, s, o);
    if ((tid & 31) == 0) red[tid >> 5] = s;
    __syncthreads();
    if (tid < 32) {
        float x = (tid < 8) ? red[tid] : 0.0f;
        #pragma unroll
        for (int o = 4; o; o >>= 1) x += __shfl_xor_sync(0xffffffffu, x, o);
        if (tid == 0) red[0] = x;
    }
    __syncthreads();
    const float inv = 1.0f / red[0];

    p[tid]       = e0 * inv;
    p[tid + 256] = e1 * inv;
}

// ---------------------------------------------------------------------------
// Kernel 4: O = P @ V per (b,h); NN GEMM M=512, N=256, K=512.
// Stores directly into concat layout [B,S,H*E].
// ---------------------------------------------------------------------------
__global__ __launch_bounds__(NTHREADS)
void attnv_kernel(const float* __restrict__ P, const float* __restrict__ V,
                  float* __restrict__ C)
{
    __shared__ float As[BK][BM];
    __shared__ float Bs[BK][BN];

    const int bh = blockIdx.z;
    const int m0 = blockIdx.y * BM;
    const int n0 = blockIdx.x * BN;
    const float* A  = P + (size_t)bh * Sn * Sn;
    const float* Bm = V + (size_t)bh * Sn * En;

    const int tid  = threadIdx.x;
    const int trow = tid >> 4;
    const int tcol = tid & 15;
    const int lrow = tid >> 2;     // A-load row 0..63
    const int lcq  = tid & 3;
    const int bkk  = tid >> 4;     // B-load k 0..15
    const int bnq  = tid & 15;     // B-load n-quad 0..15

    float acc[4][4] = {};

    for (int k0 = 0; k0 < Sn; k0 += BK) {
        float4 av = *reinterpret_cast<const float4*>(
            A + (size_t)(m0 + lrow) * Sn + k0 + lcq * 4);
        As[lcq * 4 + 0][lrow] = av.x;
        As[lcq * 4 + 1][lrow] = av.y;
        As[lcq * 4 + 2][lrow] = av.z;
        As[lcq * 4 + 3][lrow] = av.w;

        float4 bv = *reinterpret_cast<const float4*>(
            Bm + (size_t)(k0 + bkk) * En + n0 + bnq * 4);
        *reinterpret_cast<float4*>(&Bs[bkk][bnq * 4]) = bv;

        __syncthreads();
        #pragma unroll
        for (int kk = 0; kk < BK; kk++) {
            float4 a4 = *reinterpret_cast<float4*>(&As[kk][trow * 4]);
            float4 b4 = *reinterpret_cast<float4*>(&Bs[kk][tcol * 4]);
            float a[4] = {a4.x, a4.y, a4.z, a4.w};
            float b[4] = {b4.x, b4.y, b4.z, b4.w};
            #pragma unroll
            for (int i = 0; i < 4; i++)
                #pragma unroll
                for (int j = 0; j < 4; j++)
                    acc[i][j] = fmaf(a[i], b[j], acc[i][j]);
        }
        __syncthreads();
    }

    const int b = bh / Hn;
    const int h = bh % Hn;
    #pragma unroll
    for (int i = 0; i < 4; i++) {
        const int q = m0 + trow * 4 + i;
        float4 o;
        o.x = acc[i][0]; o.y = acc[i][1]; o.z = acc[i][2]; o.w = acc[i][3];
        *reinterpret_cast<float4*>(
            C + ((size_t)(b * Sn + q)) * HEn + h * En + n0 + tcol * 4) = o;
    }
}

// ---------------------------------------------------------------------------
// Kernel 5: Y = C @ Wo^T + bo ; NT GEMM M=16384, N=256, K=2048
// ---------------------------------------------------------------------------
__global__ __launch_bounds__(NTHREADS)
void outproj_kernel(const float* __restrict__ C, const float* __restrict__ Wo,
                    const float* __restrict__ bo, float* __restrict__ Y)
{
    __shared__ float As[BK][BM];
    __shared__ float Bs[BK][BN];

    const int m0 = blockIdx.y * BM;
    const int n0 = blockIdx.x * BN;

    const int tid  = threadIdx.x;
    const int trow = tid >> 4;
    const int tcol = tid & 15;
    const int lrow = tid >> 2;
    const int lcq  = tid & 3;

    float acc[4][4] = {};

    for (int k0 = 0; k0 < HEn; k0 += BK) {
        float4 av = *reinterpret_cast<const float4*>(
            C + (size_t)(m0 + lrow) * HEn + k0 + lcq * 4);
        As[lcq * 4 + 0][lrow] = av.x;
        As[lcq * 4 + 1][lrow] = av.y;
        As[lcq * 4 + 2][lrow] = av.z;
        As[lcq * 4 + 3][lrow] = av.w;

        float4 bv = *reinterpret_cast<const float4*>(
            Wo + (size_t)(n0 + lrow) * HEn + k0 + lcq * 4);
        Bs[lcq * 4 + 0][lrow] = bv.x;
        Bs[lcq * 4 + 1][lrow] = bv.y;
        Bs[lcq * 4 + 2][lrow] = bv.z;
        Bs[lcq * 4 + 3][lrow] = bv.w;

        __syncthreads();
        #pragma unroll
        for (int kk = 0; kk < BK; kk++) {
            float4 a4 = *reinterpret_cast<float4*>(&As[kk][trow * 4]);
            float4 b4 = *reinterpret_cast<float4*>(&Bs[kk][tcol * 4]);
            float a[4] = {a4.x, a4.y, a4.z, a4.w};
            float b[4] = {b4.x, b4.y, b4.z, b4.w};
            #pragma unroll
            for (int i = 0; i < 4; i++)
                #pragma unroll
                for (int j = 0; j < 4; j++)
                    acc[i][j] = fmaf(a[i], b[j], acc[i][j]);
        }
        __syncthreads();
    }

    #pragma unroll
    for (int i = 0; i < 4; i++) {
        const int gm = m0 + trow * 4 + i;
        float4 o;
        o.x = acc[i][0] + bo[n0 + tcol * 4 + 0];
        o.y = acc[i][1] + bo[n0 + tcol * 4 + 1];
        o.z = acc[i][2] + bo[n0 + tcol * 4 + 2];
        o.w = acc[i][3] + bo[n0 + tcol * 4 + 3];
        *reinterpret_cast<float4*>(Y + (size_t)gm * En + n0 + tcol * 4) = o;
    }
}

// ---------------------------------------------------------------------------
// Launch
// ---------------------------------------------------------------------------
extern "C" void kernel_launch(void* const* d_in, const int* in_sizes, int n_in,
                              void* d_out, int out_size)
{
    const float* q   = (const float*)d_in[0];
    const float* k   = (const float*)d_in[1];
    const float* v   = (const float*)d_in[2];
    const float* pad = (const float*)d_in[3];
    // d_in[4] = attn_mask (analytic causal used instead)
    const float* Wq  = (const float*)d_in[5];
    const float* Wk  = (const float*)d_in[6];
    const float* Wv  = (const float*)d_in[7];
    const float* Wo  = (const float*)d_in[8];
    const float* bo  = (const float*)d_in[9];
    float* out = (float*)d_out;

    float *gQ, *gK, *gV, *gSc, *gC;
    cudaGetSymbolAddress((void**)&gQ,  g_Q);
    cudaGetSymbolAddress((void**)&gK,  g_K);
    cudaGetSymbolAddress((void**)&gV,  g_V);
    cudaGetSymbolAddress((void**)&gSc, g_Sc);
    cudaGetSymbolAddress((void**)&gC,  g_C);

    dim3 projGrid(En / BN, Mn / BM, Hn);          // (4, 256, 8)
    proj_kernel<<<projGrid, NTHREADS>>>(q, Wq, nullptr, gQ);
    proj_kernel<<<projGrid, NTHREADS>>>(k, Wk, pad,     gK);
    proj_kernel<<<projGrid, NTHREADS>>>(v, Wv, nullptr, gV);

    dim3 scGrid(Sn / BN, Sn / BM, BHn);           // (8, 8, 256)
    scores_kernel<<<scGrid, NTHREADS>>>(gQ, gK, gSc);

    softmax_kernel<<<BHn * Sn, 256>>>(gSc);       // 131072 blocks

    dim3 avGrid(En / BN, Sn / BM, BHn);           // (4, 8, 256)
    attnv_kernel<<<avGrid, NTHREADS>>>(gSc, gV, gC);

    dim3 outGrid(En / BN, Mn / BM, 1);            // (4, 256)
    outproj_kernel<<<outGrid, NTHREADS>>>(gC, Wo, bo, out);
}

// round 3
// speedup vs baseline: 2.6977x; 2.6977x over previous
#include <cuda_runtime.h>
#include <cuda_bf16.h>
#include <cstdint>

#define Bn 32
#define Sn 512
#define En 256
#define Hn 8
#define HEn 2048
#define Mn 16384
#define BHn 256

// ---------------------------------------------------------------------------
// Scratch (device globals; allocation-free per harness rules)
// ---------------------------------------------------------------------------
__device__ float g_Q[(size_t)BHn * Sn * En];    // [B,H,S,E]
__device__ float g_K[(size_t)BHn * Sn * En];    // [B,H,S,E] padding-masked
__device__ float g_V[(size_t)BHn * Sn * En];    // [B,H,S,E]
__device__ float g_Sc[(size_t)BHn * Sn * Sn];   // [B,H,S,S]
__device__ float g_C[(size_t)Mn * HEn];         // concat [B,S,H*E]

// ---------------------------------------------------------------------------
// PTX helpers (arch-portable: ldmatrix + mma.sync, sm_80+)
// ---------------------------------------------------------------------------
__device__ __forceinline__ uint32_t smem_u32(const void* p) {
    uint32_t a;
    asm("{ .reg .u64 t; cvta.to.shared.u64 t, %1; cvt.u32.u64 %0, t; }"
        : "=r"(a) : "l"(p));
    return a;
}

__device__ __forceinline__ void ldsm_x4(uint32_t* r, uint32_t a) {
    asm volatile("ldmatrix.sync.aligned.m8n8.x4.shared.b16 {%0,%1,%2,%3}, [%4];"
                 : "=r"(r[0]), "=r"(r[1]), "=r"(r[2]), "=r"(r[3]) : "r"(a));
}
__device__ __forceinline__ void ldsm_x2(uint32_t* r, uint32_t a) {
    asm volatile("ldmatrix.sync.aligned.m8n8.x2.shared.b16 {%0,%1}, [%2];"
                 : "=r"(r[0]), "=r"(r[1]) : "r"(a));
}
__device__ __forceinline__ void mma_bf16(float* c, const uint32_t* a,
                                         const uint32_t* b) {
    asm volatile(
        "mma.sync.aligned.m16n8k16.row.col.f32.bf16.bf16.f32 "
        "{%0,%1,%2,%3}, {%4,%5,%6,%7}, {%8,%9}, {%0,%1,%2,%3};"
        : "+f"(c[0]), "+f"(c[1]), "+f"(c[2]), "+f"(c[3])
        : "r"(a[0]), "r"(a[1]), "r"(a[2]), "r"(a[3]), "r"(b[0]), "r"(b[1]));
}

// split fp32 pair into (hi, lo) bf16x2 words
__device__ __forceinline__ void split_pair(float x, float y,
                                           uint32_t& hi, uint32_t& lo) {
    __nv_bfloat162 h = __floats2bfloat162_rn(x, y);
    hi = *reinterpret_cast<uint32_t*>(&h);
    float hx = __uint_as_float(hi << 16);
    float hy = __uint_as_float(hi & 0xFFFF0000u);
    __nv_bfloat162 l = __floats2bfloat162_rn(x - hx, y - hy);
    lo = *reinterpret_cast<uint32_t*>(&l);
}

// smem layout constants: 4 tiles (Ahi,Alo,Bhi,Blo) of 128 rows x 80B, x2 stages
#define ROWB   80
#define TILE_B 10240
#define AHo    0
#define ALo    10240
#define BHo    20480
#define BLo    30720
#define STAGEB 40960
#define SMEM_BYTES (2 * STAGEB)

// ---------------------------------------------------------------------------
// Unified split-bf16 HMMA NT GEMM. 128x128 CTA tile, 256 threads (8 warps),
// warp tile 64x32, K-chunk = 32 fp32, double-buffered smem.
// MODE 0: proj: Out[b,h,s,d] = X[b,s,:]·W[h,d,:], optional pad row-scale
// MODE 2: scores: Out[bh,q,k] = (Q·K)/16, skip fully-causal tiles
// MODE 3: attnv: Out = concat[B,S,H*E]; B tile = V (transposed at staging);
//                K loop truncated at causal boundary
// MODE 4: outproj: Out[m,n] = C·Wo^T + bias
// ---------------------------------------------------------------------------
template <int MODE>
__global__ __launch_bounds__(256)
void gemm_mma(const float* __restrict__ Aall, const float* __restrict__ Ball,
              float* __restrict__ Out, const float* __restrict__ pad,
              const float* __restrict__ bias)
{
    extern __shared__ char smem[];
    const uint32_t sb = smem_u32(smem);
    const int tid = threadIdx.x, wid = tid >> 5, lane = tid & 31;
    const int m0 = blockIdx.y * 128, n0 = blockIdx.x * 128, z = blockIdx.z;

    if constexpr (MODE == 2) {
        if (n0 >= m0 + 128) return;  // fully masked: never computed, never read
    }

    const float* A;
    const float* Bp;
    int lda, nc;
    if constexpr (MODE == 0) {
        A = Aall + (size_t)m0 * En;
        Bp = Ball + (size_t)z * En * En + (size_t)n0 * En;
        lda = En; nc = En / 32;
    } else if constexpr (MODE == 2) {
        A = Aall + (size_t)z * Sn * En + (size_t)m0 * En;
        Bp = Ball + (size_t)z * Sn * En + (size_t)n0 * En;
        lda = En; nc = En / 32;
    } else if constexpr (MODE == 3) {
        A = Aall + (size_t)z * Sn * Sn + (size_t)m0 * Sn;
        Bp = Ball + (size_t)z * Sn * En;         // V [S,E]; transposed at staging
        lda = Sn; nc = (m0 + 128) / 32;          // causal truncation
    } else {
        A = Aall + (size_t)m0 * HEn;
        Bp = Ball + (size_t)n0 * HEn;
        lda = HEn; nc = HEn / 32;
    }

    float c[4][4][4] = {};
    float4 va[4], vb[4];

    auto ldA = [&](int cc) {
        #pragma unroll
        for (int i = 0; i < 4; i++) {
            int idx = i * 256 + tid, row = idx >> 3, q4 = idx & 7;
            va[i] = *reinterpret_cast<const float4*>(
                A + (size_t)row * lda + cc * 32 + q4 * 4);
        }
    };
    auto ldB = [&](int cc) {
        if constexpr (MODE == 3) {
            #pragma unroll
            for (int i = 0; i < 4; i++) {
                int idx = i * 256 + tid, kr = idx >> 5, n4 = idx & 31;
                vb[i] = *reinterpret_cast<const float4*>(
                    Bp + (size_t)(cc * 32 + kr) * En + n0 + n4 * 4);
            }
        } else {
            const int ldb = (MODE == 0 || MODE == 2) ? En : HEn;
            #pragma unroll
            for (int i = 0; i < 4; i++) {
                int idx = i * 256 + tid, row = idx >> 3, q4 = idx & 7;
                vb[i] = *reinterpret_cast<const float4*>(
                    Bp + (size_t)row * ldb + cc * 32 + q4 * 4);
            }
        }
    };
    auto stA = [&](int s) {
        char* base = smem + s * STAGEB;
        #pragma unroll
        for (int i = 0; i < 4; i++) {
            int idx = i * 256 + tid, row = idx >> 3, q4 = idx & 7;
            uint32_t h0, l0, h1, l1;
            split_pair(va[i].x, va[i].y, h0, l0);
            split_pair(va[i].z, va[i].w, h1, l1);
            int off = row * ROWB + q4 * 8;
            *reinterpret_cast<uint2*>(base + AHo + off) = make_uint2(h0, h1);
            *reinterpret_cast<uint2*>(base + ALo + off) = make_uint2(l0, l1);
        }
    };
    auto stB = [&](int s) {
        char* base = smem + s * STAGEB;
        if constexpr (MODE == 3) {
            #pragma unroll
            for (int i = 0; i < 4; i++) {
                int idx = i * 256 + tid, kr = idx >> 5, n4 = idx & 31;
                const float* vv = &vb[i].x;
                #pragma unroll
                for (int j = 0; j < 4; j++) {
                    float x = vv[j];
                    __nv_bfloat16 h = __float2bfloat16(x);
                    __nv_bfloat16 l = __float2bfloat16(x - __bfloat162float(h));
                    int off = (n4 * 4 + j) * ROWB + kr * 2;
                    *reinterpret_cast<__nv_bfloat16*>(base + BHo + off) = h;
                    *reinterpret_cast<__nv_bfloat16*>(base + BLo + off) = l;
                }
            }
        } else {
            #pragma unroll
            for (int i = 0; i < 4; i++) {
                int idx = i * 256 + tid, row = idx >> 3, q4 = idx & 7;
                uint32_t h0, l0, h1, l1;
                split_pair(vb[i].x, vb[i].y, h0, l0);
                split_pair(vb[i].z, vb[i].w, h1, l1);
                int off = row * ROWB + q4 * 8;
                *reinterpret_cast<uint2*>(base + BHo + off) = make_uint2(h0, h1);
                *reinterpret_cast<uint2*>(base + BLo + off) = make_uint2(l0, l1);
            }
        }
    };

    // prologue: stage chunk 0
    ldA(0); ldB(0);
    stA(0); stB(0);
    __syncthreads();

    const int wm = wid & 1, wn = wid >> 1;     // 2 x 4 warp grid
    const uint32_t a_lane =
        (uint32_t)((wm * 64 + (lane & 15)) * ROWB + (lane >> 4) * 16);
    const uint32_t b_lane =
        (uint32_t)((wn * 32 + (lane & 7)) * ROWB + ((lane >> 3) & 1) * 16);

    for (int cc = 0; cc < nc; ++cc) {
        if (cc + 1 < nc) { ldA(cc + 1); ldB(cc + 1); }

        const uint32_t st = sb + (cc & 1) * STAGEB;
        #pragma unroll
        for (int kb = 0; kb < 2; kb++) {
            uint32_t ah[4][4], al[4][4], bh[4][2], bl[4][2];
            #pragma unroll
            for (int ma = 0; ma < 4; ma++) {
                uint32_t ad = st + AHo + a_lane + ma * (16 * ROWB) + kb * 32;
                ldsm_x4(ah[ma], ad);
                ldsm_x4(al[ma], ad + (ALo - AHo));
            }
            #pragma unroll
            for (int na = 0; na < 4; na++) {
                uint32_t bd = st + BHo + b_lane + na * (8 * ROWB) + kb * 32;
                ldsm_x2(bh[na], bd);
                ldsm_x2(bl[na], bd + (BLo - BHo));
            }
            #pragma unroll
            for (int ma = 0; ma < 4; ma++)
                #pragma unroll
                for (int na = 0; na < 4; na++) {
                    mma_bf16(c[ma][na], ah[ma], bh[na]);
                    mma_bf16(c[ma][na], al[ma], bh[na]);
                    mma_bf16(c[ma][na], ah[ma], bl[na]);
                }
        }

        if (cc + 1 < nc) { stA((cc + 1) & 1); stB((cc + 1) & 1); }
        __syncthreads();
    }

    // ---- epilogue ----
    const int g = lane >> 2, tig = lane & 3;
    #pragma unroll
    for (int ma = 0; ma < 4; ma++) {
        const int r0 = m0 + wm * 64 + ma * 16 + g;
        const int r1 = r0 + 8;
        float s0 = 1.0f, s1 = 1.0f;
        if constexpr (MODE == 0) {
            if (pad) { s0 = pad[r0]; s1 = pad[r1]; }
        }
        #pragma unroll
        for (int na = 0; na < 4; na++) {
            const int cb = n0 + wn * 32 + na * 8 + 2 * tig;
            const float v0 = c[ma][na][0], v1 = c[ma][na][1];
            const float v2 = c[ma][na][2], v3 = c[ma][na][3];
            if constexpr (MODE == 0) {
                float* p0 = Out + (((size_t)((r0 >> 9) * Hn + z)) * Sn + (r0 & 511)) * En + cb;
                float* p1 = Out + (((size_t)((r1 >> 9) * Hn + z)) * Sn + (r1 & 511)) * En + cb;
                *reinterpret_cast<float2*>(p0) = make_float2(v0 * s0, v1 * s0);
                *reinterpret_cast<float2*>(p1) = make_float2(v2 * s1, v3 * s1);
            } else if constexpr (MODE == 2) {
                float* p0 = Out + (size_t)z * Sn * Sn + (size_t)r0 * Sn + cb;
                float* p1 = Out + (size_t)z * Sn * Sn + (size_t)r1 * Sn + cb;
                *reinterpret_cast<float2*>(p0) = make_float2(v0 * 0.0625f, v1 * 0.0625f);
                *reinterpret_cast<float2*>(p1) = make_float2(v2 * 0.0625f, v3 * 0.0625f);
            } else if constexpr (MODE == 3) {
                float* p0 = Out + ((size_t)((z >> 3) * Sn + r0)) * HEn + (z & 7) * En + cb;
                float* p1 = Out + ((size_t)((z >> 3) * Sn + r1)) * HEn + (z & 7) * En + cb;
                *reinterpret_cast<float2*>(p0) = make_float2(v0, v1);
                *reinterpret_cast<float2*>(p1) = make_float2(v2, v3);
            } else {
                const float bx = bias[cb], by = bias[cb + 1];
                float* p0 = Out + (size_t)r0 * En + cb;
                float* p1 = Out + (size_t)r1 * En + cb;
                *reinterpret_cast<float2*>(p0) = make_float2(v0 + bx, v1 + by);
                *reinterpret_cast<float2*>(p1) = make_float2(v2 + bx, v3 + by);
            }
        }
    }
}

// ---------------------------------------------------------------------------
// Causal-aware row softmax: applies the causal mask by INDEX (score memory
// beyond the diagonal is never read), writes only k < tile_end (=(q/128+1)*128)
// — exactly the region attnv consumes. k>q within the tile gets 0.
// ---------------------------------------------------------------------------
__global__ __launch_bounds__(256)
void softmax_causal(float* __restrict__ Sc)
{
    __shared__ float red[8];
    const int q = blockIdx.x & (Sn - 1);
    float* p = Sc + (size_t)blockIdx.x * Sn;
    const int tid = threadIdx.x;
    const int tend = ((q >> 7) + 1) << 7;
    const int k0 = tid, k1 = tid + 256;

    float v0 = (k0 <= q) ? p[k0] : -1e30f;
    float v1 = (k1 <= q) ? p[k1] : -1e30f;

    float m = fmaxf(v0, v1);
    #pragma unroll
    for (int o = 16; o; o >>= 1) m = fmaxf(m, __shfl_xor_sync(0xffffffffu, m, o));
    if ((tid & 31) == 0) red[tid >> 5] = m;
    __syncthreads();
    if (tid < 32) {
        float x = (tid < 8) ? red[tid] : -1e30f;
        #pragma unroll
        for (int o = 4; o; o >>= 1) x = fmaxf(x, __shfl_xor_sync(0xffffffffu, x, o));
        if (tid == 0) red[0] = x;
    }
    __syncthreads();
    m = red[0];
    __syncthreads();

    float e0 = __expf(v0 - m);
    float e1 = __expf(v1 - m);

    float s = e0 + e1;
    #pragma unroll
    for (int o = 16; o; o >>= 1) s += __shfl_xor_sync(0xffffffffu, s, o);
    if ((tid & 31) == 0) red[tid >> 5] = s;
    __syncthreads();
    if (tid < 32) {
        float x = (tid < 8) ? red[tid] : 0.0f;
        #pragma unroll
        for (int o = 4; o; o >>= 1) x += __shfl_xor_sync(0xffffffffu, x, o);
        if (tid == 0) red[0] = x;
    }
    __syncthreads();
    const float inv = 1.0f / red[0];

    if (k0 < tend) p[k0] = (k0 <= q) ? e0 * inv : 0.0f;
    if (k1 < tend) p[k1] = (k1 <= q) ? e1 * inv : 0.0f;
}

// ---------------------------------------------------------------------------
// Launch
// ---------------------------------------------------------------------------
extern "C" void kernel_launch(void* const* d_in, const int* in_sizes, int n_in,
                              void* d_out, int out_size)
{
    const float* q   = (const float*)d_in[0];
    const float* k   = (const float*)d_in[1];
    const float* v   = (const float*)d_in[2];
    const float* pad = (const float*)d_in[3];
    // d_in[4] = attn_mask (causal applied analytically)
    const float* Wq  = (const float*)d_in[5];
    const float* Wk  = (const float*)d_in[6];
    const float* Wv  = (const float*)d_in[7];
    const float* Wo  = (const float*)d_in[8];
    const float* bo  = (const float*)d_in[9];
    float* out = (float*)d_out;

    float *gQ, *gK, *gV, *gSc, *gC;
    cudaGetSymbolAddress((void**)&gQ,  g_Q);
    cudaGetSymbolAddress((void**)&gK,  g_K);
    cudaGetSymbolAddress((void**)&gV,  g_V);
    cudaGetSymbolAddress((void**)&gSc, g_Sc);
    cudaGetSymbolAddress((void**)&gC,  g_C);

    cudaFuncSetAttribute(gemm_mma<0>, cudaFuncAttributeMaxDynamicSharedMemorySize, SMEM_BYTES);
    cudaFuncSetAttribute(gemm_mma<2>, cudaFuncAttributeMaxDynamicSharedMemorySize, SMEM_BYTES);
    cudaFuncSetAttribute(gemm_mma<3>, cudaFuncAttributeMaxDynamicSharedMemorySize, SMEM_BYTES);
    cudaFuncSetAttribute(gemm_mma<4>, cudaFuncAttributeMaxDynamicSharedMemorySize, SMEM_BYTES);

    // projections: (n-tiles=2, m-tiles=128, heads=8)
    gemm_mma<0><<<dim3(2, 128, 8), 256, SMEM_BYTES>>>(q, Wq, gQ, nullptr, nullptr);
    gemm_mma<0><<<dim3(2, 128, 8), 256, SMEM_BYTES>>>(k, Wk, gK, pad,     nullptr);
    gemm_mma<0><<<dim3(2, 128, 8), 256, SMEM_BYTES>>>(v, Wv, gV, nullptr, nullptr);

    // scores: (4,4,256); upper-triangular tiles exit immediately
    gemm_mma<2><<<dim3(4, 4, 256), 256, SMEM_BYTES>>>(gQ, gK, gSc, nullptr, nullptr);

    softmax_causal<<<BHn * Sn, 256>>>(gSc);

    // attn @ V: (2,4,256), K truncated at causal boundary
    gemm_mma<3><<<dim3(2, 4, 256), 256, SMEM_BYTES>>>(gSc, gV, gC, nullptr, nullptr);

    // out projection: (2,128)
    gemm_mma<4><<<dim3(2, 128, 1), 256, SMEM_BYTES>>>(gC, Wo, out, nullptr, bo);
}

// round 4
// speedup vs baseline: 2.9586x; 1.0967x over previous
#include <cuda_runtime.h>
#include <cuda_bf16.h>
#include <cstdint>

#define Bn 32
#define Sn 512
#define En 256
#define Hn 8
#define HEn 2048
#define Mn 16384
#define BHn 256

typedef __nv_bfloat16 bf16;

// ---------------------------------------------------------------------------
// Scratch (device globals; allocation-free per harness rules). All split bf16.
// ---------------------------------------------------------------------------
__device__ bf16 g_qh[(size_t)Mn * En], g_ql[(size_t)Mn * En];
__device__ bf16 g_kh[(size_t)Mn * En], g_kl[(size_t)Mn * En];
__device__ bf16 g_vh[(size_t)Mn * En], g_vl[(size_t)Mn * En];
__device__ bf16 g_Wqh[(size_t)Hn * En * En], g_Wql[(size_t)Hn * En * En];
__device__ bf16 g_Wkh[(size_t)Hn * En * En], g_Wkl[(size_t)Hn * En * En];
__device__ bf16 g_Wvh[(size_t)Hn * En * En], g_Wvl[(size_t)Hn * En * En];
__device__ bf16 g_Woh[(size_t)En * HEn],     g_Wol[(size_t)En * HEn];
__device__ bf16 g_Qh[(size_t)BHn * Sn * En], g_Ql[(size_t)BHn * Sn * En];
__device__ bf16 g_Kh[(size_t)BHn * Sn * En], g_Kl[(size_t)BHn * Sn * En];
__device__ bf16 g_Vth[(size_t)BHn * En * Sn], g_Vtl[(size_t)BHn * En * Sn];
__device__ float g_Sc[(size_t)BHn * Sn * Sn];
__device__ bf16 g_Ph[(size_t)BHn * Sn * Sn], g_Pl[(size_t)BHn * Sn * Sn];
__device__ bf16 g_Ch[(size_t)Mn * HEn],      g_Cl[(size_t)Mn * HEn];

// ---------------------------------------------------------------------------
// PTX helpers (arch-portable: ldmatrix + mma.sync + cp.async, sm_80+)
// ---------------------------------------------------------------------------
__device__ __forceinline__ uint32_t smem_u32(const void* p) {
    uint32_t a;
    asm("{ .reg .u64 t; cvta.to.shared.u64 t, %1; cvt.u32.u64 %0, t; }"
        : "=r"(a) : "l"(p));
    return a;
}
__device__ __forceinline__ void ldsm_x4(uint32_t* r, uint32_t a) {
    asm volatile("ldmatrix.sync.aligned.m8n8.x4.shared.b16 {%0,%1,%2,%3}, [%4];"
                 : "=r"(r[0]), "=r"(r[1]), "=r"(r[2]), "=r"(r[3]) : "r"(a));
}
__device__ __forceinline__ void ldsm_x2(uint32_t* r, uint32_t a) {
    asm volatile("ldmatrix.sync.aligned.m8n8.x2.shared.b16 {%0,%1}, [%2];"
                 : "=r"(r[0]), "=r"(r[1]) : "r"(a));
}
__device__ __forceinline__ void mma_bf16(float* c, const uint32_t* a,
                                         const uint32_t* b) {
    asm volatile(
        "mma.sync.aligned.m16n8k16.row.col.f32.bf16.bf16.f32 "
        "{%0,%1,%2,%3}, {%4,%5,%6,%7}, {%8,%9}, {%0,%1,%2,%3};"
        : "+f"(c[0]), "+f"(c[1]), "+f"(c[2]), "+f"(c[3])
        : "r"(a[0]), "r"(a[1]), "r"(a[2]), "r"(a[3]), "r"(b[0]), "r"(b[1]));
}
__device__ __forceinline__ void cp16(uint32_t s, const void* g) {
    asm volatile("cp.async.cg.shared.global [%0], [%1], 16;" :: "r"(s), "l"(g));
}
#define CP_COMMIT() asm volatile("cp.async.commit_group;" ::: "memory")
#define CP_WAIT1()  asm volatile("cp.async.wait_group 1;"  ::: "memory")

// split fp32 pair into (hi, lo) bf16x2 words
__device__ __forceinline__ void split_pair(float x, float y,
                                           uint32_t& hi, uint32_t& lo) {
    __nv_bfloat162 h = __floats2bfloat162_rn(x, y);
    hi = *reinterpret_cast<uint32_t*>(&h);
    float hx = __uint_as_float(hi << 16);
    float hy = __uint_as_float(hi & 0xFFFF0000u);
    __nv_bfloat162 l = __floats2bfloat162_rn(x - hx, y - hy);
    lo = *reinterpret_cast<uint32_t*>(&l);
}

// smem: 4 tiles (Ah,Al,Bh,Bl) of 128 rows x 80B, 3 stages
#define ROWB   80
#define AHo    0
#define ALo    10240
#define BHo    20480
#define BLo    30720
#define STAGEB 40960
#define NSTAGE 3
#define SMEM_BYTES (NSTAGE * STAGEB)   // 122880

// ---------------------------------------------------------------------------
// fp32 -> split bf16 conversion (4 elems/thread)
// ---------------------------------------------------------------------------
__global__ __launch_bounds__(256)
void cvt_split_k(const float* __restrict__ src, bf16* __restrict__ hi,
                 bf16* __restrict__ lo, int n4)
{
    int i = blockIdx.x * blockDim.x + threadIdx.x;
    if (i >= n4) return;
    float4 v = reinterpret_cast<const float4*>(src)[i];
    uint32_t h0, l0, h1, l1;
    split_pair(v.x, v.y, h0, l0);
    split_pair(v.z, v.w, h1, l1);
    reinterpret_cast<uint2*>(hi)[i] = make_uint2(h0, h1);
    reinterpret_cast<uint2*>(lo)[i] = make_uint2(l0, l1);
}

// ---------------------------------------------------------------------------
// Unified split-bf16 HMMA NT GEMM, bf16 operands, cp.async 3-stage pipeline.
// 128x128 CTA tile, 256 threads (8 warps, 64x32 warp tiles), K-chunk 32.
// MODE 0: proj Q/K -> split bf16 [BH,S,E], optional pad row-scale
// MODE 1: proj V  -> split bf16 transposed [BH,E,S]
// MODE 2: scores  -> fp32 g_Sc * 1/16 (lower-triangular tiles only)
// MODE 3: attnv   -> split bf16 concat [B,S,H*E], K truncated at causal bound
// MODE 4: outproj -> fp32 d_out + bias
// ---------------------------------------------------------------------------
template <int MODE>
__global__ __launch_bounds__(256)
void gemm_bf(const bf16* __restrict__ Ah_, const bf16* __restrict__ Al_,
             const bf16* __restrict__ Bh_, const bf16* __restrict__ Bl_,
             void* __restrict__ out_h, void* __restrict__ out_l,
             const float* __restrict__ pad, const float* __restrict__ bias)
{
    extern __shared__ char smem[];
    const uint32_t sb = smem_u32(smem);
    const int tid = threadIdx.x, wid = tid >> 5, lane = tid & 31;
    const int m0 = blockIdx.y * 128, n0 = blockIdx.x * 128, z = blockIdx.z;

    if constexpr (MODE == 2) {
        if (n0 > m0) return;   // fully-masked tile: never computed, never read
    }

    const bf16 *Ah, *Al, *Bh, *Bl;
    int lda, ldb, nc;
    if constexpr (MODE <= 1) {
        size_t ao = (size_t)m0 * En;
        size_t bo = (size_t)z * En * En + (size_t)n0 * En;
        Ah = Ah_ + ao; Al = Al_ + ao; Bh = Bh_ + bo; Bl = Bl_ + bo;
        lda = En; ldb = En; nc = En / 32;
    } else if constexpr (MODE == 2) {
        size_t ao = (size_t)z * Sn * En + (size_t)m0 * En;
        size_t bo = (size_t)z * Sn * En + (size_t)n0 * En;
        Ah = Ah_ + ao; Al = Al_ + ao; Bh = Bh_ + bo; Bl = Bl_ + bo;
        lda = En; ldb = En; nc = En / 32;
    } else if constexpr (MODE == 3) {
        size_t ao = (size_t)z * Sn * Sn + (size_t)m0 * Sn;
        size_t bo = (size_t)z * En * Sn + (size_t)n0 * Sn;
        Ah = Ah_ + ao; Al = Al_ + ao; Bh = Bh_ + bo; Bl = Bl_ + bo;
        lda = Sn; ldb = Sn; nc = (m0 + 128) / 32;   // causal truncation
    } else {
        size_t ao = (size_t)m0 * HEn;
        size_t bo = (size_t)n0 * HEn;
        Ah = Ah_ + ao; Al = Al_ + ao; Bh = Bh_ + bo; Bl = Bl_ + bo;
        lda = HEn; ldb = HEn; nc = HEn / 32;
    }

    auto issue = [&](int cc) {
        const uint32_t st = sb + (uint32_t)(cc % NSTAGE) * STAGEB;
        #pragma unroll
        for (int i = 0; i < 2; i++) {
            const int idx = i * 256 + tid;
            const int row = idx >> 2, ch = idx & 3;
            const uint32_t so = (uint32_t)(row * ROWB + ch * 16);
            const size_t ga = (size_t)row * lda + (size_t)cc * 32 + ch * 8;
            const size_t gb = (size_t)row * ldb + (size_t)cc * 32 + ch * 8;
            cp16(st + AHo + so, Ah + ga);
            cp16(st + ALo + so, Al + ga);
            cp16(st + BHo + so, Bh + gb);
            cp16(st + BLo + so, Bl + gb);
        }
    };

    // prologue: 2 stages in flight
    issue(0); CP_COMMIT();
    issue(1); CP_COMMIT();

    const int wm = wid & 1, wn = wid >> 1;     // 2 x 4 warp grid
    const uint32_t a_lane =
        (uint32_t)((wm * 64 + (lane & 15)) * ROWB + (lane >> 4) * 16);
    const uint32_t b_lane =
        (uint32_t)((wn * 32 + (lane & 7)) * ROWB + ((lane >> 3) & 1) * 16);

    float c[4][4][4] = {};

    for (int cc = 0; cc < nc; ++cc) {
        CP_WAIT1();
        __syncthreads();
        if (cc + 2 < nc) issue(cc + 2);
        CP_COMMIT();

        const uint32_t st = sb + (uint32_t)(cc % NSTAGE) * STAGEB;
        #pragma unroll
        for (int kb = 0; kb < 2; kb++) {
            uint32_t ah[4][4], al[4][4], bh[4][2], bl[4][2];
            #pragma unroll
            for (int ma = 0; ma < 4; ma++) {
                uint32_t ad = st + AHo + a_lane + ma * (16 * ROWB) + kb * 32;
                ldsm_x4(ah[ma], ad);
                ldsm_x4(al[ma], ad + (ALo - AHo));
            }
            #pragma unroll
            for (int na = 0; na < 4; na++) {
                uint32_t bd = st + BHo + b_lane + na * (8 * ROWB) + kb * 32;
                ldsm_x2(bh[na], bd);
                ldsm_x2(bl[na], bd + (BLo - BHo));
            }
            #pragma unroll
            for (int ma = 0; ma < 4; ma++)
                #pragma unroll
                for (int na = 0; na < 4; na++) {
                    mma_bf16(c[ma][na], ah[ma], bh[na]);
                    mma_bf16(c[ma][na], al[ma], bh[na]);
                    mma_bf16(c[ma][na], ah[ma], bl[na]);
                }
        }
    }

    // ---- epilogue ----
    const int g = lane >> 2, tig = lane & 3;

    if constexpr (MODE == 1) {
        // stage fp32 result in smem, write transposed split bf16 [BH,E,S]
        float* ts = reinterpret_cast<float*>(smem);
        __syncthreads();
        #pragma unroll
        for (int ma = 0; ma < 4; ma++) {
            const int rl = wm * 64 + ma * 16 + g;
            #pragma unroll
            for (int na = 0; na < 4; na++) {
                const int cl = wn * 32 + na * 8 + 2 * tig;
                ts[rl * 132 + cl]           = c[ma][na][0];
                ts[rl * 132 + cl + 1]       = c[ma][na][1];
                ts[(rl + 8) * 132 + cl]     = c[ma][na][2];
                ts[(rl + 8) * 132 + cl + 1] = c[ma][na][3];
            }
        }
        __syncthreads();
        bf16* Oh = (bf16*)out_h; bf16* Ol = (bf16*)out_l;
        const int bb = m0 >> 9, sbase = m0 & 511;
        for (int i = tid; i < 128 * 64; i += 256) {
            const int d = i >> 6, s2 = (i & 63) * 2;
            float v0 = ts[s2 * 132 + d], v1 = ts[(s2 + 1) * 132 + d];
            uint32_t h, l; split_pair(v0, v1, h, l);
            size_t o = (((size_t)(bb * Hn + z)) * En + n0 + d) * Sn + sbase + s2;
            *reinterpret_cast<uint32_t*>(Oh + o) = h;
            *reinterpret_cast<uint32_t*>(Ol + o) = l;
        }
        return;
    }

    #pragma unroll
    for (int ma = 0; ma < 4; ma++) {
        const int r0 = m0 + wm * 64 + ma * 16 + g;
        const int r1 = r0 + 8;
        float s0 = 1.0f, s1 = 1.0f;
        if constexpr (MODE == 0) {
            if (pad) { s0 = pad[r0]; s1 = pad[r1]; }
        }
        #pragma unroll
        for (int na = 0; na < 4; na++) {
            const int cb = n0 + wn * 32 + na * 8 + 2 * tig;
            const float v0 = c[ma][na][0], v1 = c[ma][na][1];
            const float v2 = c[ma][na][2], v3 = c[ma][na][3];
            if constexpr (MODE == 0) {
                bf16* Oh = (bf16*)out_h; bf16* Ol = (bf16*)out_l;
                size_t o0 = (((size_t)((r0 >> 9) * Hn + z)) * Sn + (r0 & 511)) * En + cb;
                size_t o1 = (((size_t)((r1 >> 9) * Hn + z)) * Sn + (r1 & 511)) * En + cb;
                uint32_t h, l;
                split_pair(v0 * s0, v1 * s0, h, l);
                *reinterpret_cast<uint32_t*>(Oh + o0) = h;
                *reinterpret_cast<uint32_t*>(Ol + o0) = l;
                split_pair(v2 * s1, v3 * s1, h, l);
                *reinterpret_cast<uint32_t*>(Oh + o1) = h;
                *reinterpret_cast<uint32_t*>(Ol + o1) = l;
            } else if constexpr (MODE == 2) {
                float* O = (float*)out_h;
                float* p0 = O + (size_t)z * Sn * Sn + (size_t)r0 * Sn + cb;
                float* p1 = O + (size_t)z * Sn * Sn + (size_t)r1 * Sn + cb;
                *reinterpret_cast<float2*>(p0) = make_float2(v0 * 0.0625f, v1 * 0.0625f);
                *reinterpret_cast<float2*>(p1) = make_float2(v2 * 0.0625f, v3 * 0.0625f);
            } else if constexpr (MODE == 3) {
                bf16* Oh = (bf16*)out_h; bf16* Ol = (bf16*)out_l;
                size_t o0 = ((size_t)((z >> 3) * Sn + r0)) * HEn + (z & 7) * En + cb;
                size_t o1 = ((size_t)((z >> 3) * Sn + r1)) * HEn + (z & 7) * En + cb;
                uint32_t h, l;
                split_pair(v0, v1, h, l);
                *reinterpret_cast<uint32_t*>(Oh + o0) = h;
                *reinterpret_cast<uint32_t*>(Ol + o0) = l;
                split_pair(v2, v3, h, l);
                *reinterpret_cast<uint32_t*>(Oh + o1) = h;
                *reinterpret_cast<uint32_t*>(Ol + o1) = l;
            } else {
                float* O = (float*)out_h;
                const float bx = bias[cb], by = bias[cb + 1];
                float* p0 = O + (size_t)r0 * En + cb;
                float* p1 = O + (size_t)r1 * En + cb;
                *reinterpret_cast<float2*>(p0) = make_float2(v0 + bx, v1 + by);
                *reinterpret_cast<float2*>(p1) = make_float2(v2 + bx, v3 + by);
            }
        }
    }
}

// ---------------------------------------------------------------------------
// Causal row softmax: fp32 scores in, split-bf16 probs out.
// Masks by index (never reads above diagonal); writes k < tile_end only
// (exactly the region attnv consumes); k>q within tile -> 0.
// ---------------------------------------------------------------------------
__global__ __launch_bounds__(256)
void softmax_split(const float* __restrict__ Sc, bf16* __restrict__ Ph,
                   bf16* __restrict__ Pl)
{
    __shared__ float red[8];
    const int q = blockIdx.x & (Sn - 1);
    const float* p = Sc + (size_t)blockIdx.x * Sn;
    const int tid = threadIdx.x;
    const int tend = ((q >> 7) + 1) << 7;
    const int k0 = 2 * tid, k1 = 2 * tid + 1;

    float v0 = (k0 <= q) ? p[k0] : -1e30f;
    float v1 = (k1 <= q) ? p[k1] : -1e30f;

    float m = fmaxf(v0, v1);
    #pragma unroll
    for (int o = 16; o; o >>= 1) m = fmaxf(m, __shfl_xor_sync(0xffffffffu, m, o));
    if ((tid & 31) == 0) red[tid >> 5] = m;
    __syncthreads();
    if (tid < 32) {
        float x = (tid < 8) ? red[tid] : -1e30f;
        #pragma unroll
        for (int o = 4; o; o >>= 1) x = fmaxf(x, __shfl_xor_sync(0xffffffffu, x, o));
        if (tid == 0) red[0] = x;
    }
    __syncthreads();
    m = red[0];
    __syncthreads();

    float e0 = __expf(v0 - m);
    float e1 = __expf(v1 - m);

    float s = e0 + e1;
    #pragma unroll
    for (int o = 16; o; o >>= 1) s += __shfl_xor_sync(0xffffffffu, s, o);
    if ((tid & 31) == 0) red[tid >> 5] = s;
    __syncthreads();
    if (tid < 32) {
        float x = (tid < 8) ? red[tid] : 0.0f;
        #pragma unroll
        for (int o = 4; o; o >>= 1) x += __shfl_xor_sync(0xffffffffu, x, o);
        if (tid == 0) red[0] = x;
    }
    __syncthreads();
    const float inv = 1.0f / red[0];

    if (k0 < tend) {
        float p0 = (k0 <= q) ? e0 * inv : 0.0f;
        float p1 = (k1 <= q) ? e1 * inv : 0.0f;
        uint32_t h, l;
        split_pair(p0, p1, h, l);
        size_t o = (size_t)blockIdx.x * Sn + k0;
        *reinterpret_cast<uint32_t*>(Ph + o) = h;
        *reinterpret_cast<uint32_t*>(Pl + o) = l;
    }
}

// ---------------------------------------------------------------------------
// Launch
// ---------------------------------------------------------------------------
extern "C" void kernel_launch(void* const* d_in, const int* in_sizes, int n_in,
                              void* d_out, int out_size)
{
    const float* q   = (const float*)d_in[0];
    const float* k   = (const float*)d_in[1];
    const float* v   = (const float*)d_in[2];
    const float* pad = (const float*)d_in[3];
    // d_in[4] = attn_mask (causal applied analytically)
    const float* Wq  = (const float*)d_in[5];
    const float* Wk  = (const float*)d_in[6];
    const float* Wv  = (const float*)d_in[7];
    const float* Wo  = (const float*)d_in[8];
    const float* bo  = (const float*)d_in[9];
    float* out = (float*)d_out;

    bf16 *qh, *ql, *kh, *kl, *vh, *vl;
    bf16 *Wqh, *Wql, *Wkh, *Wkl, *Wvh, *Wvl, *Woh, *Wol;
    bf16 *Qh, *Ql, *Kh, *Kl, *Vth, *Vtl, *Ph, *Pl, *Ch, *Cl;
    float* Scp;
    cudaGetSymbolAddress((void**)&qh,  g_qh);  cudaGetSymbolAddress((void**)&ql,  g_ql);
    cudaGetSymbolAddress((void**)&kh,  g_kh);  cudaGetSymbolAddress((void**)&kl,  g_kl);
    cudaGetSymbolAddress((void**)&vh,  g_vh);  cudaGetSymbolAddress((void**)&vl,  g_vl);
    cudaGetSymbolAddress((void**)&Wqh, g_Wqh); cudaGetSymbolAddress((void**)&Wql, g_Wql);
    cudaGetSymbolAddress((void**)&Wkh, g_Wkh); cudaGetSymbolAddress((void**)&Wkl, g_Wkl);
    cudaGetSymbolAddress((void**)&Wvh, g_Wvh); cudaGetSymbolAddress((void**)&Wvl, g_Wvl);
    cudaGetSymbolAddress((void**)&Woh, g_Woh); cudaGetSymbolAddress((void**)&Wol, g_Wol);
    cudaGetSymbolAddress((void**)&Qh,  g_Qh);  cudaGetSymbolAddress((void**)&Ql,  g_Ql);
    cudaGetSymbolAddress((void**)&Kh,  g_Kh);  cudaGetSymbolAddress((void**)&Kl,  g_Kl);
    cudaGetSymbolAddress((void**)&Vth, g_Vth); cudaGetSymbolAddress((void**)&Vtl, g_Vtl);
    cudaGetSymbolAddress((void**)&Ph,  g_Ph);  cudaGetSymbolAddress((void**)&Pl,  g_Pl);
    cudaGetSymbolAddress((void**)&Ch,  g_Ch);  cudaGetSymbolAddress((void**)&Cl,  g_Cl);
    cudaGetSymbolAddress((void**)&Scp, g_Sc);

    cudaFuncSetAttribute(gemm_bf<0>, cudaFuncAttributeMaxDynamicSharedMemorySize, SMEM_BYTES);
    cudaFuncSetAttribute(gemm_bf<1>, cudaFuncAttributeMaxDynamicSharedMemorySize, SMEM_BYTES);
    cudaFuncSetAttribute(gemm_bf<2>, cudaFuncAttributeMaxDynamicSharedMemorySize, SMEM_BYTES);
    cudaFuncSetAttribute(gemm_bf<3>, cudaFuncAttributeMaxDynamicSharedMemorySize, SMEM_BYTES);
    cudaFuncSetAttribute(gemm_bf<4>, cudaFuncAttributeMaxDynamicSharedMemorySize, SMEM_BYTES);

    // input conversion to split bf16
    const int n4x = Mn * En / 4;          // 1048576
    const int n4w = Hn * En * En / 4;     // 131072
    cvt_split_k<<<n4x / 256, 256>>>(q,  qh,  ql,  n4x);
    cvt_split_k<<<n4x / 256, 256>>>(k,  kh,  kl,  n4x);
    cvt_split_k<<<n4x / 256, 256>>>(v,  vh,  vl,  n4x);
    cvt_split_k<<<n4w / 256, 256>>>(Wq, Wqh, Wql, n4w);
    cvt_split_k<<<n4w / 256, 256>>>(Wk, Wkh, Wkl, n4w);
    cvt_split_k<<<n4w / 256, 256>>>(Wv, Wvh, Wvl, n4w);
    cvt_split_k<<<n4w / 256, 256>>>(Wo, Woh, Wol, n4w);

    // projections: (n-tiles=2, m-tiles=128, heads=8)
    gemm_bf<0><<<dim3(2, 128, 8), 256, SMEM_BYTES>>>(qh, ql, Wqh, Wql, Qh, Ql, nullptr, nullptr);
    gemm_bf<0><<<dim3(2, 128, 8), 256, SMEM_BYTES>>>(kh, kl, Wkh, Wkl, Kh, Kl, pad, nullptr);
    gemm_bf<1><<<dim3(2, 128, 8), 256, SMEM_BYTES>>>(vh, vl, Wvh, Wvl, Vth, Vtl, nullptr, nullptr);

    // scores (4,4,256): upper-triangular tiles exit immediately
    gemm_bf<2><<<dim3(4, 4, 256), 256, SMEM_BYTES>>>(Qh, Ql, Kh, Kl, Scp, nullptr, nullptr, nullptr);

    softmax_split<<<BHn * Sn, 256>>>(Scp, Ph, Pl);

    // attn @ V: (2,4,256), K truncated at causal boundary
    gemm_bf<3><<<dim3(2, 4, 256), 256, SMEM_BYTES>>>(Ph, Pl, Vth, Vtl, Ch, Cl, nullptr, nullptr);

    // out projection: (2,128)
    gemm_bf<4><<<dim3(2, 128, 1), 256, SMEM_BYTES>>>(Ch, Cl, Woh, Wol, out, nullptr, nullptr, bo);
}